// round 3
// baseline (speedup 1.0000x reference)
#include <cuda_runtime.h>

// Problem: out[0:100]  = dgm1.flatten() : Xp[inds1[m,0], inds1[m,1]] = dot(I[row,:], p)
//          out[100:200]= dgm2.flatten() : Yp[inds2[m,0], inds2[m,1]] = dot(J[row,:], p)
// where row = ind[m,0]*28 + ind[m,1], P = 50000.
// Key insight: never materialize the full matvec — only 200 dot products needed.

#define P_DIM    50000
#define P_VEC4   (P_DIM / 4)   // 12500
#define CARD2    100           // 2*CARD entries per diagram
#define NOUT     (2 * CARD2)   // 200 output scalars
#define W_IMG    28
#define NTHREADS 512
#define NWARPS   (NTHREADS / 32)

__global__ __launch_bounds__(NTHREADS)
void gather_dot_kernel(const float* __restrict__ p,
                       const float* __restrict__ I,
                       const float* __restrict__ J,
                       const int*   __restrict__ inds1,
                       const int*   __restrict__ inds2,
                       float*       __restrict__ out)
{
    const int m = blockIdx.x;            // 0..199

    // Select matrix + index pair
    const float* mat;
    const int*   ind;
    if (m < CARD2) { mat = I; ind = inds1 + 2 * m; }
    else           { mat = J; ind = inds2 + 2 * (m - CARD2); }

    const int row = ind[0] * W_IMG + ind[1];   // broadcast load, cached

    const float4* __restrict__ rp = reinterpret_cast<const float4*>(mat + (size_t)row * P_DIM);
    const float4* __restrict__ pp = reinterpret_cast<const float4*>(p);

    // Strided vectorized dot product. 12500 float4 per row; 512 threads ->
    // ~24.4 iterations/thread. Unroll by 2 for MLP.
    float sum = 0.0f;
    int i = threadIdx.x;
    #pragma unroll 2
    for (; i + NTHREADS < P_VEC4; i += 2 * NTHREADS) {
        float4 a0 = rp[i];
        float4 b0 = pp[i];
        float4 a1 = rp[i + NTHREADS];
        float4 b1 = pp[i + NTHREADS];
        sum += a0.x * b0.x + a0.y * b0.y + a0.z * b0.z + a0.w * b0.w;
        sum += a1.x * b1.x + a1.y * b1.y + a1.z * b1.z + a1.w * b1.w;
    }
    for (; i < P_VEC4; i += NTHREADS) {
        float4 a = rp[i];
        float4 b = pp[i];
        sum += a.x * b.x + a.y * b.y + a.z * b.z + a.w * b.w;
    }

    // Warp reduction
    #pragma unroll
    for (int off = 16; off > 0; off >>= 1)
        sum += __shfl_xor_sync(0xFFFFFFFFu, sum, off);

    // Cross-warp reduction
    __shared__ float warp_sums[NWARPS];
    const int lane = threadIdx.x & 31;
    const int wid  = threadIdx.x >> 5;
    if (lane == 0) warp_sums[wid] = sum;
    __syncthreads();

    if (wid == 0) {
        float v = (lane < NWARPS) ? warp_sums[lane] : 0.0f;
        #pragma unroll
        for (int off = NWARPS / 2; off > 0; off >>= 1)
            v += __shfl_xor_sync(0xFFFFFFFFu, v, off);
        if (lane == 0) out[m] = v;
    }
}

extern "C" void kernel_launch(void* const* d_in, const int* in_sizes, int n_in,
                              void* d_out, int out_size)
{
    const float* p     = (const float*)d_in[0];   // [50000]
    const float* I     = (const float*)d_in[1];   // [784, 50000]
    const float* J     = (const float*)d_in[2];   // [784, 50000]
    const int*   inds1 = (const int*)  d_in[3];   // [100, 2]
    const int*   inds2 = (const int*)  d_in[4];   // [100, 2]
    float*       out   = (float*)d_out;           // [200]

    gather_dot_kernel<<<NOUT, NTHREADS>>>(p, I, J, inds1, inds2, out);
}